// round 11
// baseline (speedup 1.0000x reference)
#include <cuda_runtime.h>

#define T_STEPS 2048
#define BATCH   32
#define HID     256
#define INP     256
#define HSM     160          // hidden columns cached in shared memory
#define NROW    257          // 256 sources + one all-zero pad row
#define PADIDX  256          // spike-list pad index -> zero row
#define NSCAN   32           // scan CTAs (== BATCH), scheduled first
#define GEMM_CTAS 1024       // 512 bm-tiles x 2 bn-tiles
#define NCHUNK  32           // 2048 steps / 64 per chunk
#define CTAS_PER_CHUNK 32    // 16 bm-tiles x 2 bn-tiles per 64 steps

// Scratch (allocation-free rule: __device__ globals)
__device__ float g_WrT[NROW * HID];  // W_rec transposed + zero row
__device__ float g_WiT[INP * HID];   // W_in transposed
__device__ int   g_cnt[NCHUNK];      // GEMM chunk-completion counters

// ---------------------------------------------------------------------------
// Transpose weights; also zero pad row and chunk counters (runs each replay
// before the fused kernel -> counters reset for every graph execution).
// ---------------------------------------------------------------------------
__global__ void transpose_weights(const float* __restrict__ Wi,
                                  const float* __restrict__ Wr) {
    int s = blockIdx.x;
    int h = threadIdx.x;
    g_WiT[s * HID + h] = Wi[h * INP + s];
    g_WrT[s * HID + h] = Wr[h * HID + s];
    if (s == 0) {
        g_WrT[PADIDX * HID + h] = 0.0f;
        if (h < NCHUNK) g_cnt[h] = 0;
    }
}

// ---------------------------------------------------------------------------
// GEMM body: one 128x128 tile of C = input(T*B,256) @ WiT. C == d_out spike
// region (in-place reuse). After storing, bump this tile's chunk counter.
// ---------------------------------------------------------------------------
__device__ void gemm_body(float* sm, int gbid,
                          const float* __restrict__ A, float* __restrict__ C) {
    float* As = sm;           // [2][8][128]
    float* Bs = sm + 2048;    // [2][8][128]

    const int tid = threadIdx.x;
    const int tx = tid & 15;
    const int ty = tid >> 4;
    const int bmt = gbid >> 1;           // 0..511 (t-ordered)
    const int bm  = bmt * 128;
    const int bn  = (gbid & 1) * 128;

    const int arow = tid >> 1;
    const int acol = (tid & 1) * 4;
    const int brow = tid >> 5;
    const int bcol = (tid & 31) * 4;

    const float* Ap = A + (size_t)(bm + arow) * INP + acol;
    const float* Bp = g_WiT + brow * HID + bn + bcol;

    float4 a = *(const float4*)Ap;
    float4 b = *(const float4*)Bp;
    As[(acol + 0) * 128 + arow] = a.x;
    As[(acol + 1) * 128 + arow] = a.y;
    As[(acol + 2) * 128 + arow] = a.z;
    As[(acol + 3) * 128 + arow] = a.w;
    *(float4*)&Bs[brow * 128 + bcol] = b;
    __syncthreads();

    float acc[8][8];
#pragma unroll
    for (int i = 0; i < 8; ++i)
#pragma unroll
        for (int j = 0; j < 8; ++j) acc[i][j] = 0.0f;

    for (int kt = 0; kt < 32; ++kt) {
        const int cur = (kt & 1) * 1024;
        float4 an, bn4;
        if (kt < 31) {
            an  = *(const float4*)(Ap + (kt + 1) * 8);
            bn4 = *(const float4*)(Bp + (size_t)(kt + 1) * 8 * HID);
        }
#pragma unroll
        for (int k = 0; k < 8; ++k) {
            float4 a0 = *(const float4*)&As[cur + k * 128 + ty * 4];
            float4 a1 = *(const float4*)&As[cur + k * 128 + 64 + ty * 4];
            float4 b0 = *(const float4*)&Bs[cur + k * 128 + tx * 4];
            float4 b1 = *(const float4*)&Bs[cur + k * 128 + 64 + tx * 4];
            float av[8] = {a0.x, a0.y, a0.z, a0.w, a1.x, a1.y, a1.z, a1.w};
            float bv[8] = {b0.x, b0.y, b0.z, b0.w, b1.x, b1.y, b1.z, b1.w};
#pragma unroll
            for (int i = 0; i < 8; ++i)
#pragma unroll
                for (int j = 0; j < 8; ++j)
                    acc[i][j] = fmaf(av[i], bv[j], acc[i][j]);
        }
        if (kt < 31) {
            const int nxt = ((kt & 1) ^ 1) * 1024;
            As[nxt + (acol + 0) * 128 + arow] = an.x;
            As[nxt + (acol + 1) * 128 + arow] = an.y;
            As[nxt + (acol + 2) * 128 + arow] = an.z;
            As[nxt + (acol + 3) * 128 + arow] = an.w;
            *(float4*)&Bs[nxt + brow * 128 + bcol] = bn4;
        }
        __syncthreads();
    }

#pragma unroll
    for (int i = 0; i < 8; ++i) {
        const int row = bm + ((i < 4) ? (ty * 4 + i) : (64 + ty * 4 + (i - 4)));
        float4 c0 = {acc[i][0], acc[i][1], acc[i][2], acc[i][3]};
        float4 c1 = {acc[i][4], acc[i][5], acc[i][6], acc[i][7]};
        *(float4*)&C[(size_t)row * HID + bn + tx * 4]      = c0;
        *(float4*)&C[(size_t)row * HID + bn + 64 + tx * 4] = c1;
    }

    __threadfence();
    __syncthreads();
    if (tid == 0) atomicAdd(&g_cnt[bmt >> 4], 1);
}

// ---------------------------------------------------------------------------
// Scan body: one CTA per batch, 256 threads = one per hidden unit.
// Hybrid gather (warps 0-4 LDS from smem W copy, warps 5-7 LDG), vector
// ushort4 index loads, deep software pipelines (LDS 16-wide 1-deep,
// LDG 16-wide 2-deep = 32 loads in flight). Spike list padded with 32
// zero-row indices and padded count clamped to >= 32, so the branch-free
// prologues always read fully-initialized slots.
// ---------------------------------------------------------------------------
__device__ void scan_body(float* Wsm,
    const float* __restrict__ z0, const float* __restrict__ v0,
    const float* __restrict__ i0,
    float* __restrict__ out, float* __restrict__ zf,
    float* __restrict__ vf, float* __restrict__ sf)
{
    const int b = blockIdx.x;
    const int h = threadIdx.x;
    const int lane = h & 31;
    const int wid  = h >> 5;

    __shared__ unsigned masks[8];
    __shared__ alignas(16) unsigned short slist[288];   // 256 + 32 pad slots

    // preload W columns [0,HSM) for all 257 rows (incl. zero row), float4
    for (int d = h * 4; d < NROW * HSM; d += 256 * 4) {
        const int row = d / HSM, col = d % HSM;
        *(float4*)&Wsm[d] = *(const float4*)&g_WrT[row * HID + col];
    }

    float v   = v0[b * HID + h];
    float syn = i0[b * HID + h];
    float z   = z0[b * HID + h];

    float*       xop = out + b * HID + h;   // xw in, spikes out (in place)
    const float* wr  = g_WrT + h;

    for (int t = 0; t < T_STEPS; ++t) {
        if ((t & 63) == 0) {
            if (h == 0) {
                const int c = t >> 6;
                const volatile int* vc = g_cnt;
                while (vc[c] < CTAS_PER_CHUNK) __nanosleep(200);
                __threadfence();
            }
            __syncthreads();   // chunk ready (also covers Wsm preload at t=0)
        }

        const unsigned m = __ballot_sync(0xffffffffu, z > 0.0f);
        const float xwv = xop[(size_t)t * (BATCH * HID)];   // load early
        if (lane == 0) masks[wid] = m;
        __syncthreads();

        int base = 0, total = 0;
#pragma unroll
        for (int w = 0; w < 8; ++w) {
            const int c = __popc(masks[w]);
            if (w < wid) base += c;
            total += c;
        }
        if (z > 0.0f)
            slist[base + __popc(m & ((1u << lane) - 1u))] = (unsigned short)h;
        if (h < 32)
            slist[total + h] = (unsigned short)PADIDX;   // 32 zero-row pads
        int padded = (total + 31) & ~31;
        if (padded < 32) padded = 32;                    // prologue always valid
        __syncthreads();

        float r[8];
#pragma unroll
        for (int q = 0; q < 8; ++q) r[q] = 0.0f;

        if (h < HSM) {
            // LDS path: 16-wide, 1-deep prefetch
            const float* ws = Wsm + h;
            unsigned short idx[16];
            float val[16];
#pragma unroll
            for (int q = 0; q < 4; ++q)
                *(ushort4*)&idx[q * 4] = *(const ushort4*)&slist[q * 4];
#pragma unroll
            for (int q = 0; q < 16; ++q) val[q] = ws[idx[q] * HSM];
            for (int j = 16; j < padded; j += 16) {
                unsigned short ni[16];
                float nv[16];
#pragma unroll
                for (int q = 0; q < 4; ++q)
                    *(ushort4*)&ni[q * 4] = *(const ushort4*)&slist[j + q * 4];
#pragma unroll
                for (int q = 0; q < 16; ++q) nv[q] = ws[ni[q] * HSM];
#pragma unroll
                for (int q = 0; q < 16; ++q) r[q & 7] += val[q];
#pragma unroll
                for (int q = 0; q < 16; ++q) val[q] = nv[q];
            }
#pragma unroll
            for (int q = 0; q < 16; ++q) r[q & 7] += val[q];
        } else {
            // LDG path: 16-wide, 2-deep prefetch (32 loads in flight).
            // padded >= 32 guaranteed, both prologue batches fully padded.
            unsigned short ia[16], ib[16];
            float va[16], vb[16];
#pragma unroll
            for (int q = 0; q < 4; ++q)
                *(ushort4*)&ia[q * 4] = *(const ushort4*)&slist[q * 4];
#pragma unroll
            for (int q = 0; q < 16; ++q) va[q] = __ldg(wr + ia[q] * HID);
#pragma unroll
            for (int q = 0; q < 4; ++q)
                *(ushort4*)&ib[q * 4] = *(const ushort4*)&slist[16 + q * 4];
#pragma unroll
            for (int q = 0; q < 16; ++q) vb[q] = __ldg(wr + ib[q] * HID);
            for (int j = 32; j < padded; j += 16) {
                unsigned short ni[16];
                float nv[16];
#pragma unroll
                for (int q = 0; q < 4; ++q)
                    *(ushort4*)&ni[q * 4] = *(const ushort4*)&slist[j + q * 4];
#pragma unroll
                for (int q = 0; q < 16; ++q) nv[q] = __ldg(wr + ni[q] * HID);
#pragma unroll
                for (int q = 0; q < 16; ++q) r[q & 7] += va[q];
#pragma unroll
                for (int q = 0; q < 16; ++q) va[q] = vb[q];
#pragma unroll
                for (int q = 0; q < 16; ++q) vb[q] = nv[q];
            }
#pragma unroll
            for (int q = 0; q < 16; ++q) r[q & 7] += va[q];
#pragma unroll
            for (int q = 0; q < 16; ++q) r[q & 7] += vb[q];
        }
        const float rec = ((r[0] + r[1]) + (r[2] + r[3])) +
                          ((r[4] + r[5]) + (r[6] + r[7]));

        // LIF update (match reference op order; no FMA contraction)
        const float vdec = __fadd_rn(v, __fmul_rn(0.1f, __fadd_rn(__fsub_rn(0.0f, v), syn)));
        const float idec = __fsub_rn(syn, __fmul_rn(0.2f, syn));
        const float zn   = (vdec - 1.0f > 0.0f) ? 1.0f : 0.0f;
        v   = (zn > 0.0f) ? 0.0f : vdec;
        syn = __fadd_rn(__fadd_rn(idec, xwv), rec);

        xop[(size_t)t * (BATCH * HID)] = zn;   // overwrite xw with spike
        z = zn;
    }

    zf[b * HID + h] = z;
    vf[b * HID + h] = v;
    sf[b * HID + h] = syn;
}

// ---------------------------------------------------------------------------
// Fused kernel: blocks 0..31 = per-batch scan (wave-1 scheduled, persistent);
// blocks 32..1055 = GEMM tiles feeding the scan through chunk counters.
// ---------------------------------------------------------------------------
__global__ __launch_bounds__(256) void fused(
    const float* __restrict__ input,
    const float* __restrict__ z0, const float* __restrict__ v0,
    const float* __restrict__ i0,
    float* __restrict__ out, float* __restrict__ zf,
    float* __restrict__ vf, float* __restrict__ sf)
{
    extern __shared__ float dynsmem[];
    if (blockIdx.x < NSCAN)
        scan_body(dynsmem, z0, v0, i0, out, zf, vf, sf);
    else
        gemm_body(dynsmem, blockIdx.x - NSCAN, input, out);
}

// ---------------------------------------------------------------------------
extern "C" void kernel_launch(void* const* d_in, const int* in_sizes, int n_in,
                              void* d_out, int out_size) {
    const float* input = (const float*)d_in[0];  // (T, B, IN)
    const float* z0    = (const float*)d_in[1];  // (B, H)
    const float* v0    = (const float*)d_in[2];
    const float* i0    = (const float*)d_in[3];
    const float* Wi    = (const float*)d_in[4];  // (H, IN)
    const float* Wr    = (const float*)d_in[5];  // (H, H)

    float* out = (float*)d_out;                         // (T, B, H) spikes
    float* zf  = out + (size_t)T_STEPS * BATCH * HID;   // (B, H)
    float* vf  = zf + BATCH * HID;
    float* sf  = vf + BATCH * HID;

    const int smem_bytes = NROW * HSM * (int)sizeof(float);   // ~161 KB
    cudaFuncSetAttribute(fused, cudaFuncAttributeMaxDynamicSharedMemorySize,
                         smem_bytes);

    transpose_weights<<<HID, HID>>>(Wi, Wr);
    fused<<<NSCAN + GEMM_CTAS, 256, smem_bytes>>>(input, z0, v0, i0,
                                                  out, zf, vf, sf);
}

// round 12
// speedup vs baseline: 1.0891x; 1.0891x over previous
#include <cuda_runtime.h>

#define T_STEPS 2048
#define BATCH   32
#define HID     256
#define INP     256
#define HSM     160          // hidden columns cached in shared memory
#define NROW    257          // 256 sources + one all-zero pad row
#define PADIDX  256          // spike-list pad index -> zero row
#define NSCAN   32           // scan CTAs (== BATCH), scheduled first
#define GEMM_CTAS 1024       // 512 bm-tiles x 2 bn-tiles
#define NCHUNK  32           // 2048 steps / 64 per chunk
#define CTAS_PER_CHUNK 32    // 16 bm-tiles x 2 bn-tiles per 64 steps

// Scratch (allocation-free rule: __device__ globals)
__device__ float g_WrT[NROW * HID];  // W_rec transposed + zero row
__device__ float g_WiT[INP * HID];   // W_in transposed
__device__ int   g_cnt[NCHUNK];      // GEMM chunk-completion counters

// ---------------------------------------------------------------------------
// Transpose weights; zero pad row and chunk counters (runs each replay
// before the fused kernel -> counters reset for every graph execution).
// ---------------------------------------------------------------------------
__global__ void transpose_weights(const float* __restrict__ Wi,
                                  const float* __restrict__ Wr) {
    int s = blockIdx.x;
    int h = threadIdx.x;
    g_WiT[s * HID + h] = Wi[h * INP + s];
    g_WrT[s * HID + h] = Wr[h * HID + s];
    if (s == 0) {
        g_WrT[PADIDX * HID + h] = 0.0f;
        if (h < NCHUNK) g_cnt[h] = 0;
    }
}

// ---------------------------------------------------------------------------
// GEMM body: one 128x128 tile of C = input(T*B,256) @ WiT. C == d_out spike
// region (in-place reuse). After storing, bump this tile's chunk counter.
// ---------------------------------------------------------------------------
__device__ void gemm_body(float* sm, int gbid,
                          const float* __restrict__ A, float* __restrict__ C) {
    float* As = sm;           // [2][8][128]
    float* Bs = sm + 2048;    // [2][8][128]

    const int tid = threadIdx.x;
    const int tx = tid & 15;
    const int ty = tid >> 4;
    const int bmt = gbid >> 1;           // 0..511 (t-ordered)
    const int bm  = bmt * 128;
    const int bn  = (gbid & 1) * 128;

    const int arow = tid >> 1;
    const int acol = (tid & 1) * 4;
    const int brow = tid >> 5;
    const int bcol = (tid & 31) * 4;

    const float* Ap = A + (size_t)(bm + arow) * INP + acol;
    const float* Bp = g_WiT + brow * HID + bn + bcol;

    float4 a = *(const float4*)Ap;
    float4 b = *(const float4*)Bp;
    As[(acol + 0) * 128 + arow] = a.x;
    As[(acol + 1) * 128 + arow] = a.y;
    As[(acol + 2) * 128 + arow] = a.z;
    As[(acol + 3) * 128 + arow] = a.w;
    *(float4*)&Bs[brow * 128 + bcol] = b;
    __syncthreads();

    float acc[8][8];
#pragma unroll
    for (int i = 0; i < 8; ++i)
#pragma unroll
        for (int j = 0; j < 8; ++j) acc[i][j] = 0.0f;

    for (int kt = 0; kt < 32; ++kt) {
        const int cur = (kt & 1) * 1024;
        float4 an, bn4;
        if (kt < 31) {
            an  = *(const float4*)(Ap + (kt + 1) * 8);
            bn4 = *(const float4*)(Bp + (size_t)(kt + 1) * 8 * HID);
        }
#pragma unroll
        for (int k = 0; k < 8; ++k) {
            float4 a0 = *(const float4*)&As[cur + k * 128 + ty * 4];
            float4 a1 = *(const float4*)&As[cur + k * 128 + 64 + ty * 4];
            float4 b0 = *(const float4*)&Bs[cur + k * 128 + tx * 4];
            float4 b1 = *(const float4*)&Bs[cur + k * 128 + 64 + tx * 4];
            float av[8] = {a0.x, a0.y, a0.z, a0.w, a1.x, a1.y, a1.z, a1.w};
            float bv[8] = {b0.x, b0.y, b0.z, b0.w, b1.x, b1.y, b1.z, b1.w};
#pragma unroll
            for (int i = 0; i < 8; ++i)
#pragma unroll
                for (int j = 0; j < 8; ++j)
                    acc[i][j] = fmaf(av[i], bv[j], acc[i][j]);
        }
        if (kt < 31) {
            const int nxt = ((kt & 1) ^ 1) * 1024;
            As[nxt + (acol + 0) * 128 + arow] = an.x;
            As[nxt + (acol + 1) * 128 + arow] = an.y;
            As[nxt + (acol + 2) * 128 + arow] = an.z;
            As[nxt + (acol + 3) * 128 + arow] = an.w;
            *(float4*)&Bs[nxt + brow * 128 + bcol] = bn4;
        }
        __syncthreads();
    }

#pragma unroll
    for (int i = 0; i < 8; ++i) {
        const int row = bm + ((i < 4) ? (ty * 4 + i) : (64 + ty * 4 + (i - 4)));
        float4 c0 = {acc[i][0], acc[i][1], acc[i][2], acc[i][3]};
        float4 c1 = {acc[i][4], acc[i][5], acc[i][6], acc[i][7]};
        *(float4*)&C[(size_t)row * HID + bn + tx * 4]      = c0;
        *(float4*)&C[(size_t)row * HID + bn + 64 + tx * 4] = c1;
    }

    __threadfence();
    __syncthreads();
    if (tid == 0) atomicAdd(&g_cnt[bmt >> 4], 1);
}

// extract 8 ushort indices from a uint4
#define EXTRACT8(dst, I)                                  \
    dst[0] = (unsigned short)((I).x & 0xffffu);           \
    dst[1] = (unsigned short)((I).x >> 16);               \
    dst[2] = (unsigned short)((I).y & 0xffffu);           \
    dst[3] = (unsigned short)((I).y >> 16);               \
    dst[4] = (unsigned short)((I).z & 0xffffu);           \
    dst[5] = (unsigned short)((I).z >> 16);               \
    dst[6] = (unsigned short)((I).w & 0xffffu);           \
    dst[7] = (unsigned short)((I).w >> 16);

// ---------------------------------------------------------------------------
// Scan body: one CTA per batch, 256 threads = one per hidden unit.
// Hybrid gather (warps 0-4 LDS from smem W copy, warps 5-7 LDG).
// Index loads via uint4 (8 ids per broadcast). LDS loop 8-wide (pad align 8),
// LDG loop 16-wide 1-deep (pad align 16); 16 pad slots written so every read
// slot is initialized; empty-list guarded. Polls chunk counters every 64
// steps to stay behind the GEMM producer.
// ---------------------------------------------------------------------------
__device__ void scan_body(float* Wsm,
    const float* __restrict__ z0, const float* __restrict__ v0,
    const float* __restrict__ i0,
    float* __restrict__ out, float* __restrict__ zf,
    float* __restrict__ vf, float* __restrict__ sf)
{
    const int b = blockIdx.x;
    const int h = threadIdx.x;
    const int lane = h & 31;
    const int wid  = h >> 5;

    __shared__ unsigned masks[8];
    __shared__ alignas(16) unsigned short slist[272];   // 256 + 16 pad slots

    // preload W columns [0,HSM) for all 257 rows (incl. zero row), float4
    for (int d = h * 4; d < NROW * HSM; d += 256 * 4) {
        const int row = d / HSM, col = d % HSM;
        *(float4*)&Wsm[d] = *(const float4*)&g_WrT[row * HID + col];
    }

    float v   = v0[b * HID + h];
    float syn = i0[b * HID + h];
    float z   = z0[b * HID + h];

    float*       xop = out + b * HID + h;   // xw in, spikes out (in place)
    const float* wr  = g_WrT + h;

    for (int t = 0; t < T_STEPS; ++t) {
        if ((t & 63) == 0) {
            if (h == 0) {
                const int c = t >> 6;
                const volatile int* vc = g_cnt;
                while (vc[c] < CTAS_PER_CHUNK) __nanosleep(200);
                __threadfence();
            }
            __syncthreads();   // chunk ready (also covers Wsm preload at t=0)
        }

        const unsigned m = __ballot_sync(0xffffffffu, z > 0.0f);
        const float xwv = xop[(size_t)t * (BATCH * HID)];   // load early
        if (lane == 0) masks[wid] = m;
        __syncthreads();

        int base = 0, total = 0;
#pragma unroll
        for (int w = 0; w < 8; ++w) {
            const int c = __popc(masks[w]);
            if (w < wid) base += c;
            total += c;
        }
        if (z > 0.0f)
            slist[base + __popc(m & ((1u << lane) - 1u))] = (unsigned short)h;
        if (h < 16)
            slist[total + h] = (unsigned short)PADIDX;   // 16 zero-row pads
        const int padded8  = (total + 7)  & ~7;          // <= total+7
        const int padded16 = (total + 15) & ~15;         // <= total+15
        __syncthreads();

        float r[8];
#pragma unroll
        for (int q = 0; q < 8; ++q) r[q] = 0.0f;

        if (h < HSM) {
            // LDS path: 8-wide, 1-deep prefetch, uint4 index loads
            const float* ws = Wsm + h;
            if (padded8) {
                unsigned short idx[8];
                float val[8];
                uint4 I = *(const uint4*)&slist[0];
                EXTRACT8(idx, I)
#pragma unroll
                for (int q = 0; q < 8; ++q) val[q] = ws[idx[q] * HSM];
                for (int j = 8; j < padded8; j += 8) {
                    unsigned short ni[8];
                    float nv[8];
                    uint4 In = *(const uint4*)&slist[j];
                    EXTRACT8(ni, In)
#pragma unroll
                    for (int q = 0; q < 8; ++q) nv[q] = ws[ni[q] * HSM];
#pragma unroll
                    for (int q = 0; q < 8; ++q) r[q] += val[q];
#pragma unroll
                    for (int q = 0; q < 8; ++q) val[q] = nv[q];
                }
#pragma unroll
                for (int q = 0; q < 8; ++q) r[q] += val[q];
            }
        } else {
            // LDG path: 16-wide, 1-deep prefetch, uint4 index loads
            if (padded16) {
                unsigned short idx[16];
                float val[16];
                uint4 Ia = *(const uint4*)&slist[0];
                uint4 Ib = *(const uint4*)&slist[8];
                EXTRACT8(idx, Ia)
                EXTRACT8((idx + 8), Ib)
#pragma unroll
                for (int q = 0; q < 16; ++q) val[q] = __ldg(wr + idx[q] * HID);
                for (int j = 16; j < padded16; j += 16) {
                    unsigned short ni[16];
                    float nv[16];
                    uint4 Na = *(const uint4*)&slist[j];
                    uint4 Nb = *(const uint4*)&slist[j + 8];
                    EXTRACT8(ni, Na)
                    EXTRACT8((ni + 8), Nb)
#pragma unroll
                    for (int q = 0; q < 16; ++q) nv[q] = __ldg(wr + ni[q] * HID);
#pragma unroll
                    for (int q = 0; q < 16; ++q) r[q & 7] += val[q];
#pragma unroll
                    for (int q = 0; q < 16; ++q) val[q] = nv[q];
                }
#pragma unroll
                for (int q = 0; q < 16; ++q) r[q & 7] += val[q];
            }
        }
        const float rec = ((r[0] + r[1]) + (r[2] + r[3])) +
                          ((r[4] + r[5]) + (r[6] + r[7]));

        // LIF update (match reference op order; no FMA contraction)
        const float vdec = __fadd_rn(v, __fmul_rn(0.1f, __fadd_rn(__fsub_rn(0.0f, v), syn)));
        const float idec = __fsub_rn(syn, __fmul_rn(0.2f, syn));
        const float zn   = (vdec - 1.0f > 0.0f) ? 1.0f : 0.0f;
        v   = (zn > 0.0f) ? 0.0f : vdec;
        syn = __fadd_rn(__fadd_rn(idec, xwv), rec);

        xop[(size_t)t * (BATCH * HID)] = zn;   // overwrite xw with spike
        z = zn;
    }

    zf[b * HID + h] = z;
    vf[b * HID + h] = v;
    sf[b * HID + h] = syn;
}

// ---------------------------------------------------------------------------
// Fused kernel: blocks 0..31 = per-batch scan (wave-1 scheduled, persistent);
// blocks 32..1055 = GEMM tiles feeding the scan through chunk counters.
// ---------------------------------------------------------------------------
__global__ __launch_bounds__(256) void fused(
    const float* __restrict__ input,
    const float* __restrict__ z0, const float* __restrict__ v0,
    const float* __restrict__ i0,
    float* __restrict__ out, float* __restrict__ zf,
    float* __restrict__ vf, float* __restrict__ sf)
{
    extern __shared__ float dynsmem[];
    if (blockIdx.x < NSCAN)
        scan_body(dynsmem, z0, v0, i0, out, zf, vf, sf);
    else
        gemm_body(dynsmem, blockIdx.x - NSCAN, input, out);
}

// ---------------------------------------------------------------------------
extern "C" void kernel_launch(void* const* d_in, const int* in_sizes, int n_in,
                              void* d_out, int out_size) {
    const float* input = (const float*)d_in[0];  // (T, B, IN)
    const float* z0    = (const float*)d_in[1];  // (B, H)
    const float* v0    = (const float*)d_in[2];
    const float* i0    = (const float*)d_in[3];
    const float* Wi    = (const float*)d_in[4];  // (H, IN)
    const float* Wr    = (const float*)d_in[5];  // (H, H)

    float* out = (float*)d_out;                         // (T, B, H) spikes
    float* zf  = out + (size_t)T_STEPS * BATCH * HID;   // (B, H)
    float* vf  = zf + BATCH * HID;
    float* sf  = vf + BATCH * HID;

    const int smem_bytes = NROW * HSM * (int)sizeof(float);   // ~161 KB
    cudaFuncSetAttribute(fused, cudaFuncAttributeMaxDynamicSharedMemorySize,
                         smem_bytes);

    transpose_weights<<<HID, HID>>>(Wi, Wr);
    fused<<<NSCAN + GEMM_CTAS, 256, smem_bytes>>>(input, z0, v0, i0,
                                                  out, zf, vf, sf);
}